// round 6
// baseline (speedup 1.0000x reference)
#include <cuda_runtime.h>
#include <cuda_bf16.h>

#define N_BOND   100000
#define D        192
#define N_ETYPES 36
#define E_PER_T  30000
#define BATCH    256
#define N_EDGES  (N_ETYPES * E_PER_T)   // 1,080,000
#define N_SEG    (N_ETYPES * BATCH)     // 9216
#define ROWS_PER_WARP 8
#define DOT_WARPS (N_BOND / ROWS_PER_WARP)   // 12500 exactly

__device__ float g_s[N_BOND];     // per-node scalar projection h[i,:] . W_out
__device__ float g_acc[N_SEG];    // segment accumulators [type*BATCH + graph]

// ---------------------------------------------------------------------------
// Kernel 1: s[row] = dot(h[row,:], W_out).  One-shot warps, 8 rows per warp.
// Half-warp per row, 4 row-pairs -> 12 independent LDG.128 (3 KB) in flight.
// Streaming loads (__ldcs) since h is read exactly once.
// Side jobs: zero g_acc; prefetch src/seg into L2 for edge_kernel.
// ---------------------------------------------------------------------------
__global__ void dot_kernel(const float* __restrict__ h,
                           const float* __restrict__ W,
                           const int*   __restrict__ src,
                           const int*   __restrict__ seg) {
    const int tid = blockIdx.x * blockDim.x + threadIdx.x;
    if (tid < N_SEG) g_acc[tid] = 0.f;

    // Warm L2 with the edge index arrays (8.6 MB; L2 is 126 MB) using the
    // DRAM headroom of this latency-bound kernel. <=1 line pair per thread.
    {
        const int nlines = (N_EDGES * 4) / 128;   // 33750 per array
        if (tid < nlines) {
            asm volatile("prefetch.global.L2 [%0];" ::
                         "l"((const char*)src + (size_t)tid * 128));
            asm volatile("prefetch.global.L2 [%0];" ::
                         "l"((const char*)seg + (size_t)tid * 128));
        }
    }

    const int lane = threadIdx.x & 31;
    const int half = lane >> 4;           // 0 or 1
    const int hl   = lane & 15;           // lane within half-warp
    const int warp = tid >> 5;
    if (warp >= DOT_WARPS) return;

    const float4* W4 = reinterpret_cast<const float4*>(W);
    const float4 w0 = W4[hl];
    const float4 w1 = W4[16 + hl];
    const float4 w2 = W4[32 + hl];

    const int base = ROWS_PER_WARP * warp + half;   // rows base + 2j, j=0..3

    float4 a[4], b[4], c[4];
    #pragma unroll
    for (int j = 0; j < 4; j++) {
        const float4* p = reinterpret_cast<const float4*>(
            h + (size_t)(base + 2 * j) * D);
        a[j] = __ldcs(p + hl);
        b[j] = __ldcs(p + 16 + hl);
        c[j] = __ldcs(p + 32 + hl);
    }

    float acc[4];
    #pragma unroll
    for (int j = 0; j < 4; j++) {
        float t0 = a[j].x * w0.x + a[j].y * w0.y + a[j].z * w0.z + a[j].w * w0.w;
        float t1 = b[j].x * w1.x + b[j].y * w1.y + b[j].z * w1.z + b[j].w * w1.w;
        float t2 = c[j].x * w2.x + c[j].y * w2.y + c[j].z * w2.z + c[j].w * w2.w;
        acc[j] = t0 + t1 + t2;
    }

    // Width-16 reductions; 4 independent chains pipeline through the shfl unit.
    #pragma unroll
    for (int off = 8; off > 0; off >>= 1) {
        #pragma unroll
        for (int j = 0; j < 4; j++)
            acc[j] += __shfl_down_sync(0xffffffffu, acc[j], off, 16);
    }
    if (hl == 0) {
        #pragma unroll
        for (int j = 0; j < 4; j++)
            g_s[base + 2 * j] = acc[j];
    }
}

// ---------------------------------------------------------------------------
// Kernel 2: 4 edges per thread (int4), intra-thread run compaction, then
// warp-level segmented reduction over sorted keys, atomicAdd per run head.
// src/seg should be L2-resident thanks to the prefetch in dot_kernel.
// ---------------------------------------------------------------------------
__global__ void edge_kernel(const int* __restrict__ src,
                            const int* __restrict__ seg) {
    const int idx  = blockIdx.x * blockDim.x + threadIdx.x;   // pack index
    const int lane = threadIdx.x & 31;

    float val = 0.f;
    int   key = -1;
    if (idx < N_EDGES / 4) {
        const int e0 = idx * 4;
        const int t  = e0 / E_PER_T;
        int4 s4 = reinterpret_cast<const int4*>(src)[idx];
        int4 g4 = reinterpret_cast<const int4*>(seg)[idx];

        float v0 = g_s[s4.x], v1 = g_s[s4.y], v2 = g_s[s4.z], v3 = g_s[s4.w];
        const int kb = t * BATCH;
        int k0 = kb + g4.x, k1 = kb + g4.y, k2 = kb + g4.z, k3 = kb + g4.w;

        float acc = v0; int cur = k0;
        if (k1 == cur) acc += v1; else { atomicAdd(&g_acc[cur], acc); cur = k1; acc = v1; }
        if (k2 == cur) acc += v2; else { atomicAdd(&g_acc[cur], acc); cur = k2; acc = v2; }
        if (k3 == cur) acc += v3; else { atomicAdd(&g_acc[cur], acc); cur = k3; acc = v3; }
        val = acc; key = cur;   // tail run into warp stage
    }

    #pragma unroll
    for (int off = 1; off < 32; off <<= 1) {
        int   okey = __shfl_down_sync(0xffffffffu, key, off);
        float oval = __shfl_down_sync(0xffffffffu, val, off);
        if (lane + off < 32 && okey == key) val += oval;
    }
    int pkey = __shfl_up_sync(0xffffffffu, key, 1);
    bool head = (lane == 0) || (pkey != key);
    if (head && key >= 0) atomicAdd(&g_acc[key], val);
}

// ---------------------------------------------------------------------------
// Kernel 3: mask + softmax. 36 threads/graph, 8 graphs/block, 32 blocks.
// ---------------------------------------------------------------------------
__global__ void softmax_kernel(const int* __restrict__ mask,
                               float* __restrict__ out) {
    __shared__ float sv[8][N_ETYPES];
    __shared__ float sred[8];

    const int g = threadIdx.x / N_ETYPES;
    const int t = threadIdx.x % N_ETYPES;
    const int b = blockIdx.x * 8 + g;

    float x = g_acc[t * BATCH + b];
    if (mask[b * N_ETYPES + t] != 0) x = -1e9f;
    sv[g][t] = x;
    __syncthreads();

    if (t == 0) {
        float mx = sv[g][0];
        #pragma unroll
        for (int i = 1; i < N_ETYPES; i++) mx = fmaxf(mx, sv[g][i]);
        sred[g] = mx;
    }
    __syncthreads();

    float e = __expf(x - sred[g]);
    sv[g][t] = e;
    __syncthreads();

    if (t == 0) {
        float s = 0.f;
        #pragma unroll
        for (int i = 0; i < N_ETYPES; i++) s += sv[g][i];
        sred[g] = s;
    }
    __syncthreads();

    out[b * N_ETYPES + t] = e / sred[g];
}

// ---------------------------------------------------------------------------
extern "C" void kernel_launch(void* const* d_in, const int* in_sizes, int n_in,
                              void* d_out, int out_size) {
    const float* h    = (const float*)d_in[0];   // [100000,192]
    const float* Wout = (const float*)d_in[1];   // [192,1]
    const int*   src  = (const int*)d_in[2];     // [36,30000]
    const int*   seg  = (const int*)d_in[3];     // [36,30000]
    const int*   mask = (const int*)d_in[4];     // [256,36] bool -> int32
    float*       out  = (float*)d_out;           // [256,36]

    // 8 warps/block, 8 rows/warp -> 64 rows/block; 12500 warps -> 1563 blocks
    dot_kernel<<<(DOT_WARPS + 7) / 8, 256>>>(h, Wout, src, seg);
    edge_kernel<<<(N_EDGES / 4 + 255) / 256, 256>>>(src, seg);
    softmax_kernel<<<BATCH / 8, 8 * N_ETYPES>>>(mask, out);
}